// round 6
// baseline (speedup 1.0000x reference)
#include <cuda_runtime.h>
#include <cstddef>

// Problem constants
#define BB 2
#define SS 2048
#define HH 768
#define NHEAD 12
#define HD 64
#define MM (BB*SS)          // 4096
#define SCALE 0.125f        // HD^-0.5

// ---------------------------------------------------------------------------
// Device scratch
// ---------------------------------------------------------------------------
__device__ float g_q [(size_t)3*BB*NHEAD*SS*HD];
__device__ float g_k [(size_t)3*BB*NHEAD*SS*HD];
__device__ float g_v [(size_t)3*BB*NHEAD*SS*HD];
__device__ float g_vt[(size_t)3*BB*NHEAD*SS*HD];     // V transposed: [n][bh][d][s]
__device__ float g_s0[(size_t)BB*NHEAD*SS*SS];       // raw masked logits
__device__ float g_s1[(size_t)BB*NHEAD*SS*SS];
__device__ float g_s2[(size_t)BB*NHEAD*SS*SS];
__device__ float g_ctx[(size_t)3*MM*HH];
__device__ float g_wt[(size_t)12*HH*HH];             // transposed + tf32-rounded weights

// ---------------------------------------------------------------------------
// tf32 helpers.  Pre-rounded fp32 values ARE valid tf32 mma operands when
// reloaded raw, so producers round and consumers skip cvt.
// ---------------------------------------------------------------------------
__device__ __forceinline__ unsigned f2tf(float x){
    unsigned r; asm("cvt.rna.tf32.f32 %0, %1;" : "=r"(r) : "f"(x)); return r;
}
__device__ __forceinline__ float f2tf_f(float x){ return __uint_as_float(f2tf(x)); }

__device__ __forceinline__ void mma8(float c[4], const unsigned a[4], const unsigned b[2]){
    asm volatile("mma.sync.aligned.m16n8k8.row.col.f32.tf32.tf32.f32 "
        "{%0,%1,%2,%3},{%4,%5,%6,%7},{%8,%9},{%0,%1,%2,%3};"
        : "+f"(c[0]),"+f"(c[1]),"+f"(c[2]),"+f"(c[3])
        : "r"(a[0]),"r"(a[1]),"r"(a[2]),"r"(a[3]),"r"(b[0]),"r"(b[1]));
}
// smem tile: rows of 32 floats, float4-group XOR swizzle (bank-conflict free).
__device__ __forceinline__ int swz(int row, int c){ return (row<<5) + ((c ^ (row & 7))<<2); }

// cp.async 16B
__device__ __forceinline__ void cp16(float* s, const float* g){
    unsigned sa = (unsigned)__cvta_generic_to_shared(s);
    asm volatile("cp.async.cg.shared.global [%0], [%1], 16;" :: "r"(sa), "l"(g));
}
#define CP_COMMIT()   asm volatile("cp.async.commit_group;")
#define CP_WAIT(N)    asm volatile("cp.async.wait_group %0;" :: "n"(N))

// Async load of a [ROWS x 32] k-major tile (row stride ld) into swizzled smem.
template<int ROWS>
__device__ __forceinline__ void load_tile_async(float* s, const float* __restrict__ g,
                                                size_t ld, int k0, int tid){
#pragma unroll
    for(int i=0;i<ROWS*8/256;i++){
        int idx = i*256 + tid;
        int row = idx>>3, c = idx&7;
        cp16(s + swz(row,c), g + (size_t)row*ld + k0 + 4*c);
    }
}

// One BK=32 block-step. Warp tile = MI m16 x NI n8. CA/CB: cvt at load.
template<int MI,int NI,bool CA,bool CB>
__device__ __forceinline__ void mma_block(const float* sA, const float* sB,
        int wm_base, int wn_base, int gid, int tig, float acc[MI][NI][4]){
#pragma unroll
    for(int ks=0;ks<4;ks++){
        unsigned af[MI][4], bf[NI][2];
#pragma unroll
        for(int mi=0;mi<MI;mi++){
            int m = wm_base + mi*16 + gid;
            float a0 = sA[swz(m,   2*ks  )+tig];
            float a1 = sA[swz(m+8, 2*ks  )+tig];
            float a2 = sA[swz(m,   2*ks+1)+tig];
            float a3 = sA[swz(m+8, 2*ks+1)+tig];
            af[mi][0] = CA ? f2tf(a0) : __float_as_uint(a0);
            af[mi][1] = CA ? f2tf(a1) : __float_as_uint(a1);
            af[mi][2] = CA ? f2tf(a2) : __float_as_uint(a2);
            af[mi][3] = CA ? f2tf(a3) : __float_as_uint(a3);
        }
#pragma unroll
        for(int ni=0;ni<NI;ni++){
            int n = wn_base + ni*8 + gid;
            float b0 = sB[swz(n, 2*ks  )+tig];
            float b1 = sB[swz(n, 2*ks+1)+tig];
            bf[ni][0] = CB ? f2tf(b0) : __float_as_uint(b0);
            bf[ni][1] = CB ? f2tf(b1) : __float_as_uint(b1);
        }
#pragma unroll
        for(int mi=0;mi<MI;mi++)
#pragma unroll
            for(int ni=0;ni<NI;ni++)
                mma8(acc[mi][ni], af[mi], bf[ni]);
    }
}

// ---------------------------------------------------------------------------
// K0a: transpose + tf32-round the 12 weight matrices [h][e] -> g_wt[mat][e][h]
// ---------------------------------------------------------------------------
__global__ void __launch_bounds__(256) transpose_w(
    const float* __restrict__ Wq, const float* __restrict__ Wk,
    const float* __restrict__ Wv, const float* __restrict__ Wo)
{
    __shared__ float t[32][33];
    const int mat = blockIdx.z;
    const float* src = (mat<3?Wq:mat<6?Wk:mat<9?Wv:Wo) + (size_t)(mat%3)*HH*HH;
    float* dst = g_wt + (size_t)mat*HH*HH;
    const int x0 = blockIdx.x*32, y0 = blockIdx.y*32;
    const int tx = threadIdx.x & 31, ty = threadIdx.x >> 5;  // 32 x 8
#pragma unroll
    for(int r=0;r<4;r++) t[ty+8*r][tx] = f2tf_f(src[(size_t)(y0+ty+8*r)*HH + x0 + tx]);
    __syncthreads();
#pragma unroll
    for(int r=0;r<4;r++) dst[(size_t)(x0+ty+8*r)*HH + y0 + tx] = t[tx][ty+8*r];
}

// K1b: transpose V per head: [s][d] -> [d][s]  (values already tf32-rounded)
__global__ void __launch_bounds__(256) transpose_v()
{
    __shared__ float t[32][33];
    const int z = blockIdx.z;                   // n*24+bh
    const float* src = g_v  + (size_t)z*SS*HD;
    float* dst       = g_vt + (size_t)z*SS*HD;
    const int d0 = blockIdx.x*32, s0 = blockIdx.y*32;
    const int tx = threadIdx.x & 31, ty = threadIdx.x >> 5;
#pragma unroll
    for(int r=0;r<4;r++) t[ty+8*r][tx] = src[(size_t)(s0+ty+8*r)*HD + d0 + tx];
    __syncthreads();
#pragma unroll
    for(int r=0;r<4;r++) dst[(size_t)(d0+ty+8*r)*SS + s0 + tx] = t[tx][ty+8*r];
}

// ---------------------------------------------------------------------------
// Generic double-buffered GEMM body: C[AR x BR] tile, K = KTOT, MI=NI=4.
// ---------------------------------------------------------------------------
template<int KTOT,int AR,int BR,bool CA,bool CB>
__device__ __forceinline__ void gemm_body(
    float* sA, float* sB,
    const float* __restrict__ A, size_t lda,
    const float* __restrict__ B, size_t ldb,
    int tid, int wm_base, int wn_base, int gid, int tig,
    float acc[4][4][4])
{
    load_tile_async<AR>(sA, A, lda, 0, tid);
    load_tile_async<BR>(sB, B, ldb, 0, tid);
    CP_COMMIT();
    const int nk = KTOT/32;
#pragma unroll 1
    for(int kt=0; kt<nk; kt++){
        const int cur = kt & 1, nxt = cur ^ 1;
        if(kt+1 < nk){
            load_tile_async<AR>(sA + nxt*AR*32, A, lda, (kt+1)*32, tid);
            load_tile_async<BR>(sB + nxt*BR*32, B, ldb, (kt+1)*32, tid);
        }
        CP_COMMIT();
        CP_WAIT(1);
        __syncthreads();
        mma_block<4,4,CA,CB>(sA + cur*AR*32, sB + cur*BR*32, wm_base, wn_base, gid, tig, acc);
        __syncthreads();
    }
}

// ---------------------------------------------------------------------------
// K1: QKV projection.  Block 128x128. grid (6, 32, 9).
// ---------------------------------------------------------------------------
__global__ void __launch_bounds__(256,2) proj_tc(
    const float* __restrict__ X,
    const float* __restrict__ bq, const float* __restrict__ bk, const float* __restrict__ bv)
{
    extern __shared__ float sm[];
    float* sA = sm;
    float* sB = sm + 2*128*32;
    const int z = blockIdx.z, n = z%3, t = z/3;
    const float* Wt   = g_wt + (size_t)(t*3+n)*HH*HH;
    const float* bias = (t==0?bq:(t==1?bk:bv)) + (size_t)n*HH;
    float* O = (t==0?g_q:(t==1?g_k:g_v)) + (size_t)n*BB*NHEAD*SS*HD;

    const int m0 = blockIdx.y*128, e0 = blockIdx.x*128;
    const int tid = threadIdx.x, wid = tid>>5, lane = tid&31;
    const int gid = lane>>2, tig = lane&3;
    const int wm = wid & 1, wn = wid >> 1;       // 2x4 warps; warp tile 64x32

    float acc[4][4][4] = {};
    gemm_body<HH,128,128,true,false>(sA, sB, X + (size_t)m0*HH, HH, Wt + (size_t)e0*HH, HH,
                                     tid, wm*64, wn*32, gid, tig, acc);

#pragma unroll
    for(int mi=0;mi<4;mi++)
#pragma unroll
    for(int ni=0;ni<4;ni++){
        const int e = e0 + wn*32 + ni*8 + 2*tig;
        const float2 b2 = *(const float2*)(bias + e);
        const int head = e>>6, d = e&63;
#pragma unroll
        for(int h2=0;h2<2;h2++){
            int m = m0 + wm*64 + mi*16 + gid + h2*8;
            int b = m>>11, s = m & (SS-1);
            float2 o;
            o.x = f2tf_f(acc[mi][ni][h2*2+0] + b2.x);
            o.y = f2tf_f(acc[mi][ni][h2*2+1] + b2.y);
            *(float2*)(O + (((size_t)b*NHEAD + head)*SS + s)*HD + d) = o;
        }
    }
}

// ---------------------------------------------------------------------------
// K2: scores.  Block 128x128, K=64 fully resident. grid (16, 16, 72).
// Writes raw masked logits (consumed by exp, no rounding needed).
// ---------------------------------------------------------------------------
__global__ void __launch_bounds__(256,2) score_tc(const int* __restrict__ mask)
{
    extern __shared__ float sm[];
    float* sQ = sm;
    float* sK = sm + 2*128*32;
    const int z = blockIdx.z, n = z/24, bh = z%24, b = bh/NHEAD;
    const float* q = g_q + ((size_t)n*24 + bh)*SS*HD;
    const float* k = g_k + ((size_t)n*24 + bh)*SS*HD;
    float* sout = (n==0?g_s0:(n==1?g_s1:g_s2)) + (size_t)bh*SS*SS;

    const int i0 = blockIdx.y*128, j0 = blockIdx.x*128;
    const int tid = threadIdx.x, wid = tid>>5, lane = tid&31;
    const int gid = lane>>2, tig = lane&3;
    const int wm = wid & 1, wn = wid >> 1;

    load_tile_async<128>(sQ,          q + (size_t)i0*HD, HD,  0, tid);
    load_tile_async<128>(sQ + 128*32, q + (size_t)i0*HD, HD, 32, tid);
    load_tile_async<128>(sK,          k + (size_t)j0*HD, HD,  0, tid);
    load_tile_async<128>(sK + 128*32, k + (size_t)j0*HD, HD, 32, tid);
    CP_COMMIT();
    CP_WAIT(0);
    __syncthreads();

    float acc[4][4][4] = {};
    mma_block<4,4,false,false>(sQ,          sK,          wm*64, wn*32, gid, tig, acc);
    mma_block<4,4,false,false>(sQ + 128*32, sK + 128*32, wm*64, wn*32, gid, tig, acc);

#pragma unroll
    for(int mi=0;mi<4;mi++)
#pragma unroll
    for(int ni=0;ni<4;ni++){
        const int j = j0 + wn*32 + ni*8 + 2*tig;
        const bool mk0 = (mask[b*SS + j    ] == 0);
        const bool mk1 = (mask[b*SS + j + 1] == 0);
#pragma unroll
        for(int h2=0;h2<2;h2++){
            int i = i0 + wm*64 + mi*16 + gid + h2*8;
            float2 o;
            o.x = mk0 ? -1e30f : acc[mi][ni][h2*2+0]*SCALE;
            o.y = mk1 ? -1e30f : acc[mi][ni][h2*2+1]*SCALE;
            *(float2*)(sout + (size_t)i*SS + j) = o;
        }
    }
}

// ---------------------------------------------------------------------------
// K3: fused softmax + PV.  grid (16, 24): x = 128-row i-stripe, y = bh.
// Pass 1: exact row stats for s0, s1. Pass 2: per 32-wide j-tile, compute
// p_a, p_o (exact), t = s2 + 0.5(p_a+p_o), online softmax for p_c, and
// 3 PV mmas from smem tiles. ctx2 normalized at epilogue.
// ---------------------------------------------------------------------------
__global__ void __launch_bounds__(256,1) attn_pv()
{
    extern __shared__ float sm[];
    float* sp = sm;                       // p tiles [2][3][128*32]
    float* sv = sm + 24576;               // v tiles [2][3][64*32]
    float* st_m0  = sm + 24576 + 12288;   // [128] each
    float* st_l0i = st_m0 + 128;
    float* st_m1  = st_l0i + 128;
    float* st_l1i = st_m1 + 128;
    float* st_m2  = st_l1i + 128;
    float* st_l2  = st_m2 + 128;
    float* st_f   = st_l2 + 128;          // [2][128] rescale factors

    const int bh = blockIdx.y;
    const int i0 = blockIdx.x * 128;
    const int b  = bh / NHEAD, h = bh % NHEAD;

    const float* S0 = g_s0 + (size_t)bh*SS*SS + (size_t)i0*SS;
    const float* S1 = g_s1 + (size_t)bh*SS*SS + (size_t)i0*SS;
    const float* S2 = g_s2 + (size_t)bh*SS*SS + (size_t)i0*SS;
    const float* V0 = g_vt + ((size_t)0*24 + bh)*SS*HD;
    const float* V1 = g_vt + ((size_t)1*24 + bh)*SS*HD;
    const float* V2 = g_vt + ((size_t)2*24 + bh)*SS*HD;

    const int tid = threadIdx.x, lane = tid&31, wid = tid>>5;
    const int r = tid>>1, hh = tid&1;     // row 0..127, half 0/1 (16 cols each)
    const int gid = lane>>2, tig = lane&3;
    const int wm = wid & 3, wn = wid >> 2;   // 4m x 2n warps; warp tile 32x32

    // ---- pass 1: exact row stats for s0, s1 (online within thread) ----
    {
        float m0=-1e30f, l0=0.f, m1=-1e30f, l1=0.f;
        const float* r0 = S0 + (size_t)r*SS + hh*16;
        const float* r1 = S1 + (size_t)r*SS + hh*16;
#pragma unroll 1
        for(int g=0; g<64; g++){
            float v[16];
#pragma unroll
            for(int q=0;q<4;q++) *(float4*)(v+4*q) = *(const float4*)(r0 + g*32 + 4*q);
            float gm=v[0];
#pragma unroll
            for(int i=1;i<16;i++) gm=fmaxf(gm,v[i]);
            if(gm>m0){ l0*=__expf(m0-gm); m0=gm; }
            float s=0.f;
#pragma unroll
            for(int i=0;i<16;i++) s+=__expf(v[i]-m0);
            l0+=s;
#pragma unroll
            for(int q=0;q<4;q++) *(float4*)(v+4*q) = *(const float4*)(r1 + g*32 + 4*q);
            gm=v[0];
#pragma unroll
            for(int i=1;i<16;i++) gm=fmaxf(gm,v[i]);
            if(gm>m1){ l1*=__expf(m1-gm); m1=gm; }
            s=0.f;
#pragma unroll
            for(int i=0;i<16;i++) s+=__expf(v[i]-m1);
            l1+=s;
        }
        float mo=__shfl_xor_sync(0xffffffffu,m0,1), lo=__shfl_xor_sync(0xffffffffu,l0,1);
        float M=fmaxf(m0,mo), L=l0*__expf(m0-M)+lo*__expf(mo-M);
        if(hh==0){ st_m0[r]=M; st_l0i[r]=1.f/L; }
        mo=__shfl_xor_sync(0xffffffffu,m1,1); lo=__shfl_xor_sync(0xffffffffu,l1,1);
        M=fmaxf(m1,mo); L=l1*__expf(m1-M)+lo*__expf(mo-M);
        if(hh==0){ st_m1[r]=M; st_l1i[r]=1.f/L; st_m2[r]=-1e30f; st_l2[r]=0.f; }
    }
    __syncthreads();

    // ---- pass 2: PV loop ----
    float acc0[2][4][4]={}, acc1[2][4][4]={}, acc2[2][4][4]={};

    // prefetch s-tile 0
    float4 A0[4], A1[4], A2[4];
    {
        const float* a0 = S0 + (size_t)r*SS + hh*16;
        const float* a1 = S1 + (size_t)r*SS + hh*16;
        const float* a2 = S2 + (size_t)r*SS + hh*16;
#pragma unroll
        for(int q=0;q<4;q++){ A0[q]=*(const float4*)(a0+4*q);
                              A1[q]=*(const float4*)(a1+4*q);
                              A2[q]=*(const float4*)(a2+4*q); }
    }
    // V tile 0 (group 0)
    load_tile_async<64>(sv + 0,    V0, SS, 0, tid);
    load_tile_async<64>(sv + 2048, V1, SS, 0, tid);
    load_tile_async<64>(sv + 4096, V2, SS, 0, tid);
    CP_COMMIT();

#pragma unroll 1
    for(int k=0;k<64;k++){
        const int cur = k&1, nxt = cur^1;
        float* pb = sp + cur*12288;

        // compute p_a, p_o (exact) and t; store p0/p1 immediately
        const float rm0=st_m0[r], ri0=st_l0i[r], rm1=st_m1[r], ri1=st_l1i[r];
        float tv[16];
#pragma unroll
        for(int q=0;q<4;q++){
            const float* a0=(const float*)&A0[q];
            const float* a1=(const float*)&A1[q];
            const float* a2=(const float*)&A2[q];
            uint4 u0, u1;
            float pa0=__expf(a0[0]-rm0)*ri0, po0=__expf(a1[0]-rm1)*ri1;
            float pa1=__expf(a0[1]-rm0)*ri0, po1=__expf(a1[1]-rm1)*ri1;
            float pa2=__expf(a0[2]-rm0)*ri0, po2=__expf(a1[2]-rm1)*ri1;
            float pa3=__expf(a0[3]-rm0)*ri0, po3=__expf(a1[3]-rm1)*ri1;
            tv[4*q+0]=a2[0]+0.5f*(pa0+po0);
            tv[4*q+1]=a2[1]+0.5f*(pa1+po1);
            tv[4*q+2]=a2[2]+0.5f*(pa2+po2);
            tv[4*q+3]=a2[3]+0.5f*(pa3+po3);
            u0.x=f2tf(pa0); u0.y=f2tf(pa1); u0.z=f2tf(pa2); u0.w=f2tf(pa3);
            u1.x=f2tf(po0); u1.y=f2tf(po1); u1.z=f2tf(po2); u1.w=f2tf(po3);
            *(uint4*)(pb        + swz(r,hh*4+q)) = u0;
            *(uint4*)(pb + 4096 + swz(r,hh*4+q)) = u1;
        }
        // online softmax update for t
        float tm=tv[0];
#pragma unroll
        for(int i=1;i<16;i++) tm=fmaxf(tm,tv[i]);
        tm=fmaxf(tm,__shfl_xor_sync(0xffffffffu,tm,1));
        const float mold = st_m2[r];
        const float mnew = fmaxf(mold,tm);
        float ps=0.f;
#pragma unroll
        for(int q=0;q<4;q++){
            uint4 u2;
            float e0=__expf(tv[4*q+0]-mnew); ps+=e0;
            float e1=__expf(tv[4*q+1]-mnew); ps+=e1;
            float e2=__expf(tv[4*q+2]-mnew); ps+=e2;
            float e3=__expf(tv[4*q+3]-mnew); ps+=e3;
            u2.x=f2tf(e0); u2.y=f2tf(e1); u2.z=f2tf(e2); u2.w=f2tf(e3);
            *(uint4*)(pb + 8192 + swz(r,hh*4+q)) = u2;
        }
        ps += __shfl_xor_sync(0xffffffffu,ps,1);
        const float fct = __expf(mold-mnew);
        if(hh==0){ st_m2[r]=mnew; st_l2[r]=st_l2[r]*fct+ps; st_f[cur*128+r]=fct; }

        // prefetch s-tile k+1 (fills during mma phase)
        if(k<63){
            const float* a0 = S0 + (size_t)r*SS + (k+1)*32 + hh*16;
            const float* a1 = S1 + (size_t)r*SS + (k+1)*32 + hh*16;
            const float* a2 = S2 + (size_t)r*SS + (k+1)*32 + hh*16;
#pragma unroll
            for(int q=0;q<4;q++){ A0[q]=*(const float4*)(a0+4*q);
                                  A1[q]=*(const float4*)(a1+4*q);
                                  A2[q]=*(const float4*)(a2+4*q); }
            // V tile k+1
            load_tile_async<64>(sv + nxt*6144 + 0,    V0, SS, (k+1)*32, tid);
            load_tile_async<64>(sv + nxt*6144 + 2048, V1, SS, (k+1)*32, tid);
            load_tile_async<64>(sv + nxt*6144 + 4096, V2, SS, (k+1)*32, tid);
            CP_COMMIT();
            CP_WAIT(1);
        } else {
            CP_WAIT(0);
        }
        __syncthreads();

        // rescale ctx2 accumulators by this tile's factor (per fragment row)
        {
            const float* fb = st_f + cur*128 + wm*32;
            float f00 = fb[gid],      f01 = fb[gid+8];
            float f10 = fb[16+gid],   f11 = fb[16+gid+8];
#pragma unroll
            for(int ni=0;ni<4;ni++){
                acc2[0][ni][0]*=f00; acc2[0][ni][1]*=f00; acc2[0][ni][2]*=f01; acc2[0][ni][3]*=f01;
                acc2[1][ni][0]*=f10; acc2[1][ni][1]*=f10; acc2[1][ni][2]*=f11; acc2[1][ni][3]*=f11;
            }
        }
        // 3 PV mmas
        float* vb = sv + cur*6144;
        mma_block<2,4,false,false>(pb,        vb,        wm*32, wn*32, gid, tig, acc0);
        mma_block<2,4,false,false>(pb + 4096, vb + 2048, wm*32, wn*32, gid, tig, acc1);
        mma_block<2,4,false,false>(pb + 8192, vb + 4096, wm*32, wn*32, gid, tig, acc2);
        // no second sync: next iteration writes the other buffer
    }
    __syncthreads();

    // ---- epilogue ----
    float i200 = 1.f/st_l2[wm*32+gid],    i201 = 1.f/st_l2[wm*32+gid+8];
    float i210 = 1.f/st_l2[wm*32+16+gid], i211 = 1.f/st_l2[wm*32+16+gid+8];
#pragma unroll
    for(int mi=0;mi<2;mi++)
#pragma unroll
    for(int ni=0;ni<4;ni++){
        const int d = wn*32 + ni*8 + 2*tig;
        const float s0f = mi ? i210 : i200;
        const float s1f = mi ? i211 : i201;
#pragma unroll
        for(int h2=0;h2<2;h2++){
            const int i = i0 + wm*32 + mi*16 + gid + h2*8;
            const float sc = h2 ? s1f : s0f;
            float2 o;
            size_t base = ((size_t)b*SS + i)*HH + h*HD + d;
            o.x = f2tf_f(acc0[mi][ni][h2*2+0]); o.y = f2tf_f(acc0[mi][ni][h2*2+1]);
            *(float2*)(g_ctx + base) = o;
            o.x = f2tf_f(acc1[mi][ni][h2*2+0]); o.y = f2tf_f(acc1[mi][ni][h2*2+1]);
            *(float2*)(g_ctx + (size_t)BB*SS*HH + base) = o;
            o.x = f2tf_f(acc2[mi][ni][h2*2+0]*sc); o.y = f2tf_f(acc2[mi][ni][h2*2+1]*sc);
            *(float2*)(g_ctx + (size_t)2*BB*SS*HH + base) = o;
        }
    }
}

// ---------------------------------------------------------------------------
// K5: output projection.  Block 128x128. grid (6, 32, 3).
// ---------------------------------------------------------------------------
__global__ void __launch_bounds__(256,2) outproj_tc(
    const float* __restrict__ bo, float* __restrict__ out)
{
    extern __shared__ float sm[];
    float* sA = sm;
    float* sB = sm + 2*128*32;
    const int n = blockIdx.z;
    const float* X    = g_ctx + (size_t)n*MM*HH;
    const float* Wt   = g_wt + (size_t)(9+n)*HH*HH;
    const float* bias = bo + (size_t)n*HH;
    float* O = out + (size_t)n*MM*HH;

    const int m0 = blockIdx.y*128, e0 = blockIdx.x*128;
    const int tid = threadIdx.x, wid = tid>>5, lane = tid&31;
    const int gid = lane>>2, tig = lane&3;
    const int wm = wid & 1, wn = wid >> 1;

    float acc[4][4][4] = {};
    gemm_body<HH,128,128,false,false>(sA, sB, X + (size_t)m0*HH, HH, Wt + (size_t)e0*HH, HH,
                                      tid, wm*64, wn*32, gid, tig, acc);

#pragma unroll
    for(int mi=0;mi<4;mi++)
#pragma unroll
    for(int ni=0;ni<4;ni++){
        const int e = e0 + wn*32 + ni*8 + 2*tig;
        const float2 b2 = *(const float2*)(bias + e);
#pragma unroll
        for(int h2=0;h2<2;h2++){
            int m = m0 + wm*64 + mi*16 + gid + h2*8;
            float2 o; o.x = acc[mi][ni][h2*2+0] + b2.x; o.y = acc[mi][ni][h2*2+1] + b2.y;
            *(float2*)(O + (size_t)m*HH + e) = o;
        }
    }
}

// ---------------------------------------------------------------------------
// Launch
// ---------------------------------------------------------------------------
extern "C" void kernel_launch(void* const* d_in, const int* in_sizes, int n_in,
                              void* d_out, int out_size)
{
    (void)in_sizes; (void)n_in; (void)out_size;
    const float* hidden = (const float*)d_in[0];
    // d_in[1] aspect_weights, d_in[2] opinion_weights: per-query-row biases cancel in softmax
    const int*   mask   = (const int*)  d_in[3];
    const float* Wq = (const float*)d_in[4];  const float* bq = (const float*)d_in[5];
    const float* Wk = (const float*)d_in[6];  const float* bk = (const float*)d_in[7];
    const float* Wv = (const float*)d_in[8];  const float* bv = (const float*)d_in[9];
    const float* Wo = (const float*)d_in[10]; const float* bo = (const float*)d_in[11];
    float* out = (float*)d_out;

    const int smemAB   = (2*128*32 + 2*128*32) * 4;             // 64 KB
    const int smemAttn = (24576 + 12288 + 6*128 + 256) * 4;     // ~148 KB
    cudaFuncSetAttribute(proj_tc,    cudaFuncAttributeMaxDynamicSharedMemorySize, smemAB);
    cudaFuncSetAttribute(score_tc,   cudaFuncAttributeMaxDynamicSharedMemorySize, smemAB);
    cudaFuncSetAttribute(attn_pv,    cudaFuncAttributeMaxDynamicSharedMemorySize, smemAttn);
    cudaFuncSetAttribute(outproj_tc, cudaFuncAttributeMaxDynamicSharedMemorySize, smemAB);

    transpose_w<<<dim3(24,24,12), 256>>>(Wq, Wk, Wv, Wo);
    proj_tc    <<<dim3(6, 32, 9), 256, smemAB>>>(hidden, bq, bk, bv);
    transpose_v<<<dim3(2, 64, 72), 256>>>();
    score_tc   <<<dim3(16, 16, 72), 256, smemAB>>>(mask);
    attn_pv    <<<dim3(16, 24), 256, smemAttn>>>();
    outproj_tc <<<dim3(6, 32, 3), 256, smemAB>>>(bo, out);
}

// round 7
// speedup vs baseline: 1.6249x; 1.6249x over previous
#include <cuda_runtime.h>
#include <cuda_fp16.h>
#include <cstddef>

// Problem constants
#define BB 2
#define SS 2048
#define HH 768
#define NHEAD 12
#define HD 64
#define MM (BB*SS)          // 4096
#define SCALE 0.125f        // HD^-0.5

// ---------------------------------------------------------------------------
// Device scratch
// ---------------------------------------------------------------------------
__device__ __half g_hh[(size_t)MM*HH];                 // hidden in fp16
__device__ __half g_q [(size_t)3*BB*NHEAD*SS*HD];
__device__ __half g_k [(size_t)3*BB*NHEAD*SS*HD];
__device__ __half g_v [(size_t)3*BB*NHEAD*SS*HD];
__device__ __half g_vt[(size_t)3*BB*NHEAD*SS*HD];      // V transposed: [n][bh][d][s]
__device__ float  g_s0[(size_t)BB*NHEAD*SS*SS];        // raw masked logits (fp32)
__device__ float  g_s1[(size_t)BB*NHEAD*SS*SS];
__device__ float  g_s2[(size_t)BB*NHEAD*SS*SS];
__device__ __half g_p0[(size_t)BB*NHEAD*SS*SS];        // probabilities (fp16)
__device__ __half g_p1[(size_t)BB*NHEAD*SS*SS];
__device__ __half g_p2[(size_t)BB*NHEAD*SS*SS];
__device__ __half g_ctx[(size_t)3*MM*HH];
__device__ __half g_wt[(size_t)12*HH*HH];              // transposed fp16 weights

// ---------------------------------------------------------------------------
// fp16 mma helpers (m16n8k16, fp32 accumulate)
// ---------------------------------------------------------------------------
__device__ __forceinline__ void mma16(float c[4], const unsigned a[4], const unsigned b[2]){
    asm volatile("mma.sync.aligned.m16n8k16.row.col.f32.f16.f16.f32 "
        "{%0,%1,%2,%3},{%4,%5,%6,%7},{%8,%9},{%0,%1,%2,%3};"
        : "+f"(c[0]),"+f"(c[1]),"+f"(c[2]),"+f"(c[3])
        : "r"(a[0]),"r"(a[1]),"r"(a[2]),"r"(a[3]),"r"(b[0]),"r"(b[1]));
}
// smem tile: rows of 64 halfs (=32 uints =128B), 16B-group XOR swizzle.
// u = half2-column 0..31; returns uint index.
__device__ __forceinline__ int swzu(int row, int u){
    return (row<<5) + (((u>>2) ^ (row&7))<<2) + (u&3);
}

// cp.async 16B (8 halfs)
__device__ __forceinline__ void cp16h(unsigned* s, const __half* g){
    unsigned sa = (unsigned)__cvta_generic_to_shared(s);
    asm volatile("cp.async.cg.shared.global [%0], [%1], 16;" :: "r"(sa), "l"(g));
}
#define CP_COMMIT()   asm volatile("cp.async.commit_group;")
#define CP_WAIT(N)    asm volatile("cp.async.wait_group %0;" :: "n"(N))

// Async load of a [ROWS x 64] k-major half tile (row stride ld halfs) into smem.
template<int ROWS>
__device__ __forceinline__ void load_tile_async_h(unsigned* s, const __half* __restrict__ g,
                                                  size_t ld, int k0, int tid){
#pragma unroll
    for(int i=0;i<ROWS*8/256;i++){
        int idx = i*256 + tid;
        int row = idx>>3, c = idx&7;
        cp16h(s + (row<<5) + ((c ^ (row&7))<<2), g + (size_t)row*ld + k0 + 8*c);
    }
}

// One BK=64 block-step. Warp tile = MI m16 x NI n8. 4 mmas of K=16.
template<int MI,int NI>
__device__ __forceinline__ void mma_block_h(const unsigned* sA, const unsigned* sB,
        int wm_base, int wn_base, int gid, int tig, float acc[MI][NI][4]){
#pragma unroll
    for(int ks=0;ks<4;ks++){
        const int u0 = ks*8 + tig, u1 = u0 + 4;
        unsigned af[MI][4], bf[NI][2];
#pragma unroll
        for(int mi=0;mi<MI;mi++){
            int m = wm_base + mi*16 + gid;
            af[mi][0] = sA[swzu(m,   u0)];
            af[mi][1] = sA[swzu(m+8, u0)];
            af[mi][2] = sA[swzu(m,   u1)];
            af[mi][3] = sA[swzu(m+8, u1)];
        }
#pragma unroll
        for(int ni=0;ni<NI;ni++){
            int n = wn_base + ni*8 + gid;
            bf[ni][0] = sB[swzu(n, u0)];
            bf[ni][1] = sB[swzu(n, u1)];
        }
#pragma unroll
        for(int mi=0;mi<MI;mi++)
#pragma unroll
            for(int ni=0;ni<NI;ni++)
                mma16(acc[mi][ni], af[mi], bf[ni]);
    }
}

// ---------------------------------------------------------------------------
// K0: convert hidden fp32 -> fp16.  8 elts/thread. grid 1536.
// ---------------------------------------------------------------------------
__global__ void __launch_bounds__(256) conv_hidden(const float* __restrict__ X)
{
    size_t i = ((size_t)blockIdx.x*256 + threadIdx.x)*8;
    float4 a = *(const float4*)(X + i);
    float4 b = *(const float4*)(X + i + 4);
    __align__(16) __half2 h[4];
    h[0] = __floats2half2_rn(a.x, a.y);
    h[1] = __floats2half2_rn(a.z, a.w);
    h[2] = __floats2half2_rn(b.x, b.y);
    h[3] = __floats2half2_rn(b.z, b.w);
    *(uint4*)(g_hh + i) = *(uint4*)h;
}

// ---------------------------------------------------------------------------
// K0a: transpose + fp16-convert the 12 weight matrices [h][e] -> g_wt[mat][e][h]
// ---------------------------------------------------------------------------
__global__ void __launch_bounds__(256) transpose_w(
    const float* __restrict__ Wq, const float* __restrict__ Wk,
    const float* __restrict__ Wv, const float* __restrict__ Wo)
{
    __shared__ __half t[32][33];
    const int mat = blockIdx.z;
    const float* src = (mat<3?Wq:mat<6?Wk:mat<9?Wv:Wo) + (size_t)(mat%3)*HH*HH;
    __half* dst = g_wt + (size_t)mat*HH*HH;
    const int x0 = blockIdx.x*32, y0 = blockIdx.y*32;
    const int tx = threadIdx.x & 31, ty = threadIdx.x >> 5;  // 32 x 8
#pragma unroll
    for(int r=0;r<4;r++) t[ty+8*r][tx] = __float2half_rn(src[(size_t)(y0+ty+8*r)*HH + x0 + tx]);
    __syncthreads();
#pragma unroll
    for(int r=0;r<4;r++) dst[(size_t)(x0+ty+8*r)*HH + y0 + tx] = t[tx][ty+8*r];
}

// K1b: transpose V per head: [s][d] -> [d][s]  (fp16)
__global__ void __launch_bounds__(256) transpose_v()
{
    __shared__ __half t[32][33];
    const int z = blockIdx.z;                   // n*24+bh
    const __half* src = g_v  + (size_t)z*SS*HD;
    __half* dst       = g_vt + (size_t)z*SS*HD;
    const int d0 = blockIdx.x*32, s0 = blockIdx.y*32;
    const int tx = threadIdx.x & 31, ty = threadIdx.x >> 5;
#pragma unroll
    for(int r=0;r<4;r++) t[ty+8*r][tx] = src[(size_t)(s0+ty+8*r)*HD + d0 + tx];
    __syncthreads();
#pragma unroll
    for(int r=0;r<4;r++) dst[(size_t)(d0+ty+8*r)*SS + s0 + tx] = t[tx][ty+8*r];
}

// ---------------------------------------------------------------------------
// Generic double-buffered fp16 GEMM body: C[AR x BR], K = KTOT, MI=NI=4, BK=64.
// ---------------------------------------------------------------------------
template<int KTOT,int AR,int BR>
__device__ __forceinline__ void gemm_body_h(
    unsigned* sA, unsigned* sB,                 // sA: 2*AR*32 uints, sB: 2*BR*32
    const __half* __restrict__ A, size_t lda,
    const __half* __restrict__ B, size_t ldb,
    int tid, int wm_base, int wn_base, int gid, int tig,
    float acc[4][4][4])
{
    load_tile_async_h<AR>(sA, A, lda, 0, tid);
    load_tile_async_h<BR>(sB, B, ldb, 0, tid);
    CP_COMMIT();
    const int nk = KTOT/64;
#pragma unroll 1
    for(int kt=0; kt<nk; kt++){
        const int cur = kt & 1, nxt = cur ^ 1;
        if(kt+1 < nk){
            load_tile_async_h<AR>(sA + nxt*AR*32, A, lda, (kt+1)*64, tid);
            load_tile_async_h<BR>(sB + nxt*BR*32, B, ldb, (kt+1)*64, tid);
        }
        CP_COMMIT();
        CP_WAIT(1);
        __syncthreads();
        mma_block_h<4,4>(sA + cur*AR*32, sB + cur*BR*32, wm_base, wn_base, gid, tig, acc);
        __syncthreads();
    }
}

// ---------------------------------------------------------------------------
// K1: QKV projection.  Block 128x128. grid (6, 32, 9). fp16 in, fp16 out.
// ---------------------------------------------------------------------------
__global__ void __launch_bounds__(256,2) proj_tc(
    const float* __restrict__ bq, const float* __restrict__ bk, const float* __restrict__ bv)
{
    extern __shared__ unsigned smu[];
    unsigned* sA = smu;
    unsigned* sB = smu + 2*128*32;
    const int z = blockIdx.z, n = z%3, t = z/3;
    const __half* Wt  = g_wt + (size_t)(t*3+n)*HH*HH;
    const float* bias = (t==0?bq:(t==1?bk:bv)) + (size_t)n*HH;
    __half* O = (t==0?g_q:(t==1?g_k:g_v)) + (size_t)n*BB*NHEAD*SS*HD;

    const int m0 = blockIdx.y*128, e0 = blockIdx.x*128;
    const int tid = threadIdx.x, wid = tid>>5, lane = tid&31;
    const int gid = lane>>2, tig = lane&3;
    const int wm = wid & 1, wn = wid >> 1;       // 2x4 warps; warp tile 64x32

    float acc[4][4][4] = {};
    gemm_body_h<HH,128,128>(sA, sB, g_hh + (size_t)m0*HH, HH, Wt + (size_t)e0*HH, HH,
                            tid, wm*64, wn*32, gid, tig, acc);

#pragma unroll
    for(int mi=0;mi<4;mi++)
#pragma unroll
    for(int ni=0;ni<4;ni++){
        const int e = e0 + wn*32 + ni*8 + 2*tig;
        const float2 b2 = *(const float2*)(bias + e);
        const int head = e>>6, d = e&63;
#pragma unroll
        for(int h2=0;h2<2;h2++){
            int m = m0 + wm*64 + mi*16 + gid + h2*8;
            int b = m>>11, s = m & (SS-1);
            __half2 o = __floats2half2_rn(acc[mi][ni][h2*2+0] + b2.x,
                                          acc[mi][ni][h2*2+1] + b2.y);
            *(__half2*)(O + (((size_t)b*NHEAD + head)*SS + s)*HD + d) = o;
        }
    }
}

// ---------------------------------------------------------------------------
// K2: scores.  Block 128x128, K=64 = one BK tile (no k-loop). grid (16,16,72).
// Writes raw masked fp32 logits.
// ---------------------------------------------------------------------------
__global__ void __launch_bounds__(256,2) score_tc(const int* __restrict__ mask)
{
    extern __shared__ unsigned smu[];
    unsigned* sQ = smu;               // 128*32 uints
    unsigned* sK = smu + 128*32;
    const int z = blockIdx.z, n = z/24, bh = z%24, b = bh/NHEAD;
    const __half* q = g_q + ((size_t)n*24 + bh)*SS*HD;
    const __half* k = g_k + ((size_t)n*24 + bh)*SS*HD;
    float* sout = (n==0?g_s0:(n==1?g_s1:g_s2)) + (size_t)bh*SS*SS;

    const int i0 = blockIdx.y*128, j0 = blockIdx.x*128;
    const int tid = threadIdx.x, wid = tid>>5, lane = tid&31;
    const int gid = lane>>2, tig = lane&3;
    const int wm = wid & 1, wn = wid >> 1;

    load_tile_async_h<128>(sQ, q + (size_t)i0*HD, HD, 0, tid);
    load_tile_async_h<128>(sK, k + (size_t)j0*HD, HD, 0, tid);
    CP_COMMIT();
    CP_WAIT(0);
    __syncthreads();

    float acc[4][4][4] = {};
    mma_block_h<4,4>(sQ, sK, wm*64, wn*32, gid, tig, acc);

#pragma unroll
    for(int mi=0;mi<4;mi++)
#pragma unroll
    for(int ni=0;ni<4;ni++){
        const int j = j0 + wn*32 + ni*8 + 2*tig;
        const bool mk0 = (mask[b*SS + j    ] == 0);
        const bool mk1 = (mask[b*SS + j + 1] == 0);
#pragma unroll
        for(int h2=0;h2<2;h2++){
            int i = i0 + wm*64 + mi*16 + gid + h2*8;
            float2 o;
            o.x = mk0 ? -1e30f : acc[mi][ni][h2*2+0]*SCALE;
            o.y = mk1 ? -1e30f : acc[mi][ni][h2*2+1]*SCALE;
            *(float2*)(sout + (size_t)i*SS + j) = o;
        }
    }
}

// ---------------------------------------------------------------------------
// K3: merged softmax.  Reads fp32 s0..s2, writes fp16 p0..p2.
// grid 49152 rows, 256 threads, 8 elems/thread.
// ---------------------------------------------------------------------------
__device__ __forceinline__ float warpMax(float v){
#pragma unroll
    for(int o=16;o;o>>=1) v = fmaxf(v, __shfl_xor_sync(0xffffffffu, v, o));
    return v;
}
__device__ __forceinline__ float warpSum(float v){
#pragma unroll
    for(int o=16;o;o>>=1) v += __shfl_xor_sync(0xffffffffu, v, o);
    return v;
}

__global__ void __launch_bounds__(256) softmax_all()
{
    const size_t row = (size_t)blockIdx.x * SS;
    const float* p0 = g_s0 + row;
    const float* p1 = g_s1 + row;
    const float* p2 = g_s2 + row;
    __half* q0 = g_p0 + row;
    __half* q1 = g_p1 + row;
    __half* q2 = g_p2 + row;
    const int tid = threadIdx.x, lane = tid&31, warp = tid>>5;

    float v0[8], v1[8], v2[8];
    *(float4*)(v0  ) = *(const float4*)(p0 + tid*8);
    *(float4*)(v0+4) = *(const float4*)(p0 + tid*8 + 4);
    *(float4*)(v1  ) = *(const float4*)(p1 + tid*8);
    *(float4*)(v1+4) = *(const float4*)(p1 + tid*8 + 4);
    *(float4*)(v2  ) = *(const float4*)(p2 + tid*8);
    *(float4*)(v2+4) = *(const float4*)(p2 + tid*8 + 4);

    __shared__ float rA[8], rB[8];
    __shared__ float bA, bB;

    float m0 = v0[0], m1 = v1[0];
#pragma unroll
    for(int i=1;i<8;i++){ m0 = fmaxf(m0, v0[i]); m1 = fmaxf(m1, v1[i]); }
    m0 = warpMax(m0); m1 = warpMax(m1);
    if(lane==0){ rA[warp]=m0; rB[warp]=m1; }
    __syncthreads();
    if(tid==0){ float a=rA[0], c=rB[0];
        for(int i=1;i<8;i++){ a=fmaxf(a,rA[i]); c=fmaxf(c,rB[i]); } bA=a; bB=c; }
    __syncthreads();
    const float M0=bA, M1=bB;

    float s0=0.f, s1=0.f;
#pragma unroll
    for(int i=0;i<8;i++){ v0[i]=__expf(v0[i]-M0); s0+=v0[i];
                          v1[i]=__expf(v1[i]-M1); s1+=v1[i]; }
    s0 = warpSum(s0); s1 = warpSum(s1);
    if(lane==0){ rA[warp]=s0; rB[warp]=s1; }
    __syncthreads();
    if(tid==0){ float a=0,c=0; for(int i=0;i<8;i++){a+=rA[i]; c+=rB[i];}
        bA=1.0f/a; bB=1.0f/c; }
    __syncthreads();
    const float inv0=bA, inv1=bB;

    float t[8];
    __align__(16) __half2 h0[4], h1[4];
#pragma unroll
    for(int i=0;i<8;i++){
        v0[i] *= inv0; v1[i] *= inv1;
        t[i] = v2[i] + 0.5f*(v0[i] + v1[i]);
    }
#pragma unroll
    for(int i=0;i<4;i++){
        h0[i] = __floats2half2_rn(v0[2*i], v0[2*i+1]);
        h1[i] = __floats2half2_rn(v1[2*i], v1[2*i+1]);
    }
    *(uint4*)(q0 + tid*8) = *(uint4*)h0;
    *(uint4*)(q1 + tid*8) = *(uint4*)h1;

    float m2 = t[0];
#pragma unroll
    for(int i=1;i<8;i++) m2 = fmaxf(m2, t[i]);
    m2 = warpMax(m2);
    if(lane==0) rA[warp]=m2;
    __syncthreads();
    if(tid==0){ float a=rA[0]; for(int i=1;i<8;i++) a=fmaxf(a,rA[i]); bA=a; }
    __syncthreads();
    const float M2=bA;

    float s2=0.f;
#pragma unroll
    for(int i=0;i<8;i++){ t[i]=__expf(t[i]-M2); s2+=t[i]; }
    s2 = warpSum(s2);
    __syncthreads();
    if(lane==0) rA[warp]=s2;
    __syncthreads();
    if(tid==0){ float a=0; for(int i=0;i<8;i++) a+=rA[i]; bA=1.0f/a; }
    __syncthreads();
    const float inv2=bA;
    __align__(16) __half2 h2[4];
#pragma unroll
    for(int i=0;i<4;i++)
        h2[i] = __floats2half2_rn(t[2*i]*inv2, t[2*i+1]*inv2);
    *(uint4*)(q2 + tid*8) = *(uint4*)h2;
}

// ---------------------------------------------------------------------------
// K4: ctx = P @ V.  Block 256x64, warps 4m x 2n. grid (8, 72). K=2048, BK=64.
// ---------------------------------------------------------------------------
__global__ void __launch_bounds__(256,2) ctx_tc()
{
    extern __shared__ unsigned smu[];
    unsigned* sA = smu;               // 2*256*32
    unsigned* sB = smu + 2*256*32;    // 2*64*32
    const int z = blockIdx.y, n = z/24, bh = z%24, b = bh/NHEAD, h = bh%NHEAD;
    const __half* P  = (n==0?g_p0:(n==1?g_p1:g_p2)) + (size_t)bh*SS*SS;
    const __half* Vt = g_vt + ((size_t)n*24 + bh)*SS*HD;
    const int i0 = blockIdx.x*256;

    const int tid = threadIdx.x, wid = tid>>5, lane = tid&31;
    const int gid = lane>>2, tig = lane&3;
    const int wm = wid & 3, wn = wid >> 2;   // 4x2 warps; warp tile 64x32

    float acc[4][4][4] = {};
    gemm_body_h<SS,256,64>(sA, sB, P + (size_t)i0*SS, SS, Vt, SS,
                           tid, wm*64, wn*32, gid, tig, acc);

#pragma unroll
    for(int mi=0;mi<4;mi++)
#pragma unroll
    for(int ni=0;ni<4;ni++){
        const int d = wn*32 + ni*8 + 2*tig;
#pragma unroll
        for(int h2=0;h2<2;h2++){
            int i = i0 + wm*64 + mi*16 + gid + h2*8;
            __half2 o = __floats2half2_rn(acc[mi][ni][h2*2+0], acc[mi][ni][h2*2+1]);
            *(__half2*)(g_ctx + (((size_t)n*BB + b)*SS + i)*HH + h*HD + d) = o;
        }
    }
}

// ---------------------------------------------------------------------------
// K5: output projection.  Block 128x128. grid (6, 32, 3). fp32 out + bias.
// ---------------------------------------------------------------------------
__global__ void __launch_bounds__(256,2) outproj_tc(
    const float* __restrict__ bo, float* __restrict__ out)
{
    extern __shared__ unsigned smu[];
    unsigned* sA = smu;
    unsigned* sB = smu + 2*128*32;
    const int n = blockIdx.z;
    const __half* X   = g_ctx + (size_t)n*MM*HH;
    const __half* Wt  = g_wt + (size_t)(9+n)*HH*HH;
    const float* bias = bo + (size_t)n*HH;
    float* O = out + (size_t)n*MM*HH;

    const int m0 = blockIdx.y*128, e0 = blockIdx.x*128;
    const int tid = threadIdx.x, wid = tid>>5, lane = tid&31;
    const int gid = lane>>2, tig = lane&3;
    const int wm = wid & 1, wn = wid >> 1;

    float acc[4][4][4] = {};
    gemm_body_h<HH,128,128>(sA, sB, X + (size_t)m0*HH, HH, Wt + (size_t)e0*HH, HH,
                            tid, wm*64, wn*32, gid, tig, acc);

#pragma unroll
    for(int mi=0;mi<4;mi++)
#pragma unroll
    for(int ni=0;ni<4;ni++){
        const int e = e0 + wn*32 + ni*8 + 2*tig;
        const float2 b2 = *(const float2*)(bias + e);
#pragma unroll
        for(int h2=0;h2<2;h2++){
            int m = m0 + wm*64 + mi*16 + gid + h2*8;
            float2 o; o.x = acc[mi][ni][h2*2+0] + b2.x; o.y = acc[mi][ni][h2*2+1] + b2.y;
            *(float2*)(O + (size_t)m*HH + e) = o;
        }
    }
}

// ---------------------------------------------------------------------------
// Launch
// ---------------------------------------------------------------------------
extern "C" void kernel_launch(void* const* d_in, const int* in_sizes, int n_in,
                              void* d_out, int out_size)
{
    (void)in_sizes; (void)n_in; (void)out_size;
    const float* hidden = (const float*)d_in[0];
    // d_in[1] aspect_weights, d_in[2] opinion_weights: per-query-row biases cancel in softmax
    const int*   mask   = (const int*)  d_in[3];
    const float* Wq = (const float*)d_in[4];  const float* bq = (const float*)d_in[5];
    const float* Wk = (const float*)d_in[6];  const float* bk = (const float*)d_in[7];
    const float* Wv = (const float*)d_in[8];  const float* bv = (const float*)d_in[9];
    const float* Wo = (const float*)d_in[10]; const float* bo = (const float*)d_in[11];
    float* out = (float*)d_out;

    const int smemAB  = (2*128*32 + 2*128*32) * 4;   // 64 KB (proj/outproj)
    const int smemSc  = (128*32 + 128*32) * 4;       // 32 KB (score)
    const int smemCtx = (2*256*32 + 2*64*32) * 4;    // 80 KB (ctx)
    cudaFuncSetAttribute(proj_tc,    cudaFuncAttributeMaxDynamicSharedMemorySize, smemAB);
    cudaFuncSetAttribute(score_tc,   cudaFuncAttributeMaxDynamicSharedMemorySize, smemSc);
    cudaFuncSetAttribute(ctx_tc,     cudaFuncAttributeMaxDynamicSharedMemorySize, smemCtx);
    cudaFuncSetAttribute(outproj_tc, cudaFuncAttributeMaxDynamicSharedMemorySize, smemAB);

    conv_hidden<<<dim3(MM*HH/2048), 256>>>(hidden);
    transpose_w<<<dim3(24,24,12), 256>>>(Wq, Wk, Wv, Wo);
    proj_tc    <<<dim3(6, 32, 9), 256, smemAB>>>(bq, bk, bv);
    transpose_v<<<dim3(2, 64, 72), 256>>>();
    score_tc   <<<dim3(16, 16, 72), 256, smemSc>>>(mask);
    softmax_all<<<dim3(BB*NHEAD*SS), 256>>>();
    ctx_tc     <<<dim3(8, 72), 256, smemCtx>>>();
    outproj_tc <<<dim3(6, 32, 3), 256, smemAB>>>(bo, out);
}